// round 10
// baseline (speedup 1.0000x reference)
#include <cuda_runtime.h>
#include <cuda_fp16.h>
#include <math.h>
#include <stdint.h>

// Problem constants (fixed by the dataset)
#define HEADS   8
#define OUT_F   64
#define HO      512          // HEADS * OUT_F
#define IN_F    256
#define MAXN    50048        // padded node count (multiple of 128)
#define MAXE    1600000

// ---------------- scratch (static __device__ globals, no runtime alloc) -----
__device__ __align__(16) static __half g_th[(size_t)MAXN * HO]; // 51.2 MB fp16 t (gather)
__device__ __align__(16) static float  g_w[(size_t)MAXN * HEADS]; // exp(logit)
__device__ static int g_cnt[MAXN];
__device__ static int g_rowptr[MAXN + 1];
__device__ static int g_cur[MAXN];
__device__ static int g_col[MAXE];
__device__ static int g_part[128];

// ---------------- CSR build -------------------------------------------------
__global__ void k_hist(const int* __restrict__ src, int E) {
    int i = blockIdx.x * blockDim.x + threadIdx.x;
    if (i < E) atomicAdd(&g_cnt[src[i]], 1);
}

__global__ void k_scan1(int N) {
    __shared__ int s[1024];
    int tid = threadIdx.x;
    int i = blockIdx.x * 1024 + tid;
    int v = (i < N) ? g_cnt[i] : 0;
    s[tid] = v;
    __syncthreads();
    #pragma unroll
    for (int off = 1; off < 1024; off <<= 1) {
        int add = (tid >= off) ? s[tid - off] : 0;
        __syncthreads();
        s[tid] += add;
        __syncthreads();
    }
    if (i < N) g_rowptr[i + 1] = s[tid];
    if (tid == 1023) g_part[blockIdx.x] = s[1023];
}

__global__ void k_scan2(int B) {
    int run = 0;
    for (int b = 0; b < B; ++b) { int t = g_part[b]; g_part[b] = run; run += t; }
}

__global__ void k_scan3(int N) {
    int i = blockIdx.x * 1024 + threadIdx.x;
    if (i < N) {
        int rp = g_rowptr[i + 1] + g_part[blockIdx.x];
        g_rowptr[i + 1] = rp;
        if (i + 1 < N) g_cur[i + 1] = rp;
    }
    if (i == 0) { g_rowptr[0] = 0; g_cur[0] = 0; }
}

__global__ void k_scatter(const int* __restrict__ src, const int* __restrict__ dst, int E) {
    int i = blockIdx.x * blockDim.x + threadIdx.x;
    if (i < E) {
        int p = atomicAdd(&g_cur[src[i]], 1);
        g_col[p] = dst[i];
    }
}

// ---------------- tf32 MMA GEMM (cp.async double-buffered) ------------------
// t = x (M x 256) · Ws^T (256 x 512). BM=BN=128, BK=32, 2-stage pipeline.
// smem row-major [row][k] with pad 36 (36 mod 32 = 4 => fragment loads map
// addr%32 == lane: conflict-free). Fragments converted to tf32 with round-to-
// nearest (cvt.rna) at register load (validated: unbiased error profile).
// Epilogue: fp16 t store + fused per-row exp(logit) for the block's 2 heads.
#define SMPAD 36
#define ABUF  4608            // 128*36 floats per stage
#define GEMM_SMEM ((2*ABUF*2 + 128 + 256) * 4)   // 75264 B

__device__ __forceinline__ void cp16(void* smem_dst, const void* gsrc, int nbytes) {
    uint32_t s = (uint32_t)__cvta_generic_to_shared(smem_dst);
    asm volatile("cp.async.ca.shared.global [%0], [%1], 16, %2;\n"
                 :: "r"(s), "l"(gsrc), "r"(nbytes));
}

__device__ __forceinline__ uint32_t rna(float x) {
    uint32_t u;
    asm("cvt.rna.tf32.f32 %0, %1;" : "=r"(u) : "f"(x));
    return u;
}

__global__ __launch_bounds__(256) void k_gemm(const float* __restrict__ A,
                                              const float* __restrict__ B,
                                              const float* __restrict__ As_in,
                                              int M) {
    extern __shared__ float dyn[];
    float* pA      = dyn;                 // [2][128][SMPAD]
    float* pB      = dyn + 2 * ABUF;      // [2][128][SMPAD]
    float* s_ar    = dyn + 4 * ABUF;      // [128]
    float* s_logit = s_ar + 128;          // [128][2]

    int tid  = threadIdx.x;
    int lane = tid & 31;
    int warp = tid >> 5;
    int wm   = (warp & 1) * 64;
    int wn   = (warp >> 1) * 32;
    int m0   = blockIdx.x * 128;
    int n0   = blockIdx.y * 128;

    if (tid < 128) {
        int c = n0 + tid;
        s_ar[tid] = As_in[(c >> 6) * 128 + 64 + (c & 63)];
    }
    s_logit[tid] = 0.f;   // 256 floats total, 256 threads

    float acc[4][4][4];
    #pragma unroll
    for (int mi = 0; mi < 4; ++mi)
        #pragma unroll
        for (int ni = 0; ni < 4; ++ni)
            #pragma unroll
            for (int j = 0; j < 4; ++j) acc[mi][ni][j] = 0.f;

    // stage issue: 128 rows x 32 floats for A and B = 1024 16B chunks each
    #define ISSUE(k0, buf)                                                     \
        do {                                                                   \
            _Pragma("unroll")                                                  \
            for (int r = 0; r < 4; ++r) {                                      \
                int id  = r * 256 + tid;                                       \
                int row = id >> 3;                                             \
                int c4  = (id & 7) * 4;                                        \
                cp16(&pA[(buf) * ABUF + row * SMPAD + c4],                     \
                     &A[(size_t)(m0 + row) * IN_F + (k0) + c4],                \
                     (m0 + row < M) ? 16 : 0);                                 \
                cp16(&pB[(buf) * ABUF + row * SMPAD + c4],                     \
                     &B[(size_t)(n0 + row) * IN_F + (k0) + c4], 16);           \
            }                                                                  \
            asm volatile("cp.async.commit_group;\n");                          \
        } while (0)

    ISSUE(0, 0);

    int lr = lane >> 2;   // 0..7
    int lc = lane & 3;    // 0..3

    for (int k0i = 0; k0i < 8; ++k0i) {
        int cur = k0i & 1;
        if (k0i < 7) {
            ISSUE((k0i + 1) * 32, cur ^ 1);
            asm volatile("cp.async.wait_group 1;\n");
        } else {
            asm volatile("cp.async.wait_group 0;\n");
        }
        __syncthreads();

        const float* Ab = pA + cur * ABUF;
        const float* Bb = pB + cur * ABUF;
        #pragma unroll
        for (int kk = 0; kk < 32; kk += 8) {
            uint32_t afr[4][4];
            uint32_t bfr[4][2];
            #pragma unroll
            for (int mi = 0; mi < 4; ++mi) {
                int rb = wm + mi * 16;
                afr[mi][0] = rna(Ab[(rb + lr    ) * SMPAD + kk + lc    ]);
                afr[mi][1] = rna(Ab[(rb + lr + 8) * SMPAD + kk + lc    ]);
                afr[mi][2] = rna(Ab[(rb + lr    ) * SMPAD + kk + lc + 4]);
                afr[mi][3] = rna(Ab[(rb + lr + 8) * SMPAD + kk + lc + 4]);
            }
            #pragma unroll
            for (int ni = 0; ni < 4; ++ni) {
                int nb = wn + ni * 8;
                bfr[ni][0] = rna(Bb[(nb + lr) * SMPAD + kk + lc    ]);
                bfr[ni][1] = rna(Bb[(nb + lr) * SMPAD + kk + lc + 4]);
            }
            #pragma unroll
            for (int mi = 0; mi < 4; ++mi)
                #pragma unroll
                for (int ni = 0; ni < 4; ++ni) {
                    asm volatile(
                        "mma.sync.aligned.m16n8k8.row.col.f32.tf32.tf32.f32 "
                        "{%0,%1,%2,%3}, {%4,%5,%6,%7}, {%8,%9}, {%0,%1,%2,%3};\n"
                        : "+f"(acc[mi][ni][0]), "+f"(acc[mi][ni][1]),
                          "+f"(acc[mi][ni][2]), "+f"(acc[mi][ni][3])
                        : "r"(afr[mi][0]), "r"(afr[mi][1]),
                          "r"(afr[mi][2]), "r"(afr[mi][3]),
                          "r"(bfr[ni][0]), "r"(bfr[ni][1]));
                }
        }
        __syncthreads();
    }

    // epilogue: fp16 t store + block-local logit reduction
    int head_local = warp >> 2;   // warps 0-3 -> head 0 of block; 4-7 -> head 1
    #pragma unroll
    for (int mi = 0; mi < 4; ++mi) {
        int r0 = m0 + wm + mi * 16 + lr;
        int r1 = r0 + 8;
        float p0 = 0.f, p1 = 0.f;
        #pragma unroll
        for (int ni = 0; ni < 4; ++ni) {
            int cl = wn + ni * 8 + lc * 2;    // block-local col
            int c  = n0 + cl;
            p0 = fmaf(acc[mi][ni][0], s_ar[cl], fmaf(acc[mi][ni][1], s_ar[cl + 1], p0));
            p1 = fmaf(acc[mi][ni][2], s_ar[cl], fmaf(acc[mi][ni][3], s_ar[cl + 1], p1));
            if (r0 < M)
                *(__half2*)&g_th[(size_t)r0 * HO + c] =
                    __floats2half2_rn(acc[mi][ni][0], acc[mi][ni][1]);
            if (r1 < M)
                *(__half2*)&g_th[(size_t)r1 * HO + c] =
                    __floats2half2_rn(acc[mi][ni][2], acc[mi][ni][3]);
        }
        atomicAdd(&s_logit[(wm + mi * 16 + lr    ) * 2 + head_local], p0);
        atomicAdd(&s_logit[(wm + mi * 16 + lr + 8) * 2 + head_local], p1);
    }
    __syncthreads();

    if (tid < 128 && m0 + tid < M) {
        int hb = blockIdx.y * 2;
        g_w[(size_t)(m0 + tid) * HEADS + hb    ] = expf(s_logit[tid * 2 + 0]);
        g_w[(size_t)(m0 + tid) * HEADS + hb + 1] = expf(s_logit[tid * 2 + 1]);
    }
}

// ---------------- aggregation + ELU (fp16 gather, post-normalize) -----------
// 256 threads = 2 independent 128-thread halves, one node each. Within a half,
// thread j owns out[n, 4j..4j+3]; head h = j/16. Column indices staged through
// shared memory; halves synchronize with NAMED barriers (ids 1/2, 128 threads)
// so divergent edge counts between the two nodes cannot deadlock.
// h[n] = (sum_e w_d * t_d) / (sum_e w_d): softmax normalization at the end
// (Al and the max-shift cancel in the ratio).
__global__ __launch_bounds__(256) void k_agg(float* __restrict__ out, int N) {
    __shared__ int s_col[2][128];

    int tid  = threadIdx.x;
    int half = tid >> 7;           // 0 or 1
    int ltid = tid & 127;
    int n    = blockIdx.x * 2 + half;
    if (n >= N) return;

    int rs = g_rowptr[n];
    int re = g_rowptr[n + 1];
    int h  = ltid >> 4;
    int bar = half + 1;

    if (re == rs) {  // no outgoing edges: out = elu(0) = 0
        *(float4*)&out[(size_t)n * HO + ltid * 4] = make_float4(0.f, 0.f, 0.f, 0.f);
        return;
    }

    float  ws  = 0.f;
    float4 acc = make_float4(0.f, 0.f, 0.f, 0.f);
    const uint2* th2 = (const uint2*)g_th;   // 8 bytes = 4 fp16 per thread

    for (int base = rs; base < re; base += 128) {
        int nload = min(128, re - base);
        asm volatile("bar.sync %0, 128;" :: "r"(bar) : "memory");
        if (ltid < nload) s_col[half][ltid] = __ldg(&g_col[base + ltid]);
        asm volatile("bar.sync %0, 128;" :: "r"(bar) : "memory");
        #pragma unroll 4
        for (int e = 0; e < nload; ++e) {
            int d = s_col[half][e];
            float wv = __ldg(&g_w[(size_t)d * 8 + h]);
            ws += wv;
            uint2 v = th2[(size_t)d * 128 + ltid];   // coalesced 1KB row gather
            float2 f0 = __half22float2(*(__half2*)&v.x);
            float2 f1 = __half22float2(*(__half2*)&v.y);
            acc.x = fmaf(wv, f0.x, acc.x);
            acc.y = fmaf(wv, f0.y, acc.y);
            acc.z = fmaf(wv, f1.x, acc.z);
            acc.w = fmaf(wv, f1.y, acc.w);
        }
    }

    float inv = 1.f / ws;
    acc.x *= inv; acc.y *= inv; acc.z *= inv; acc.w *= inv;

    float4 r;
    r.x = acc.x > 0.f ? acc.x : expm1f(acc.x);
    r.y = acc.y > 0.f ? acc.y : expm1f(acc.y);
    r.z = acc.z > 0.f ? acc.z : expm1f(acc.z);
    r.w = acc.w > 0.f ? acc.w : expm1f(acc.w);
    __stcs((float4*)&out[(size_t)n * HO + ltid * 4], r);  // stream out, keep t in L2
}

// ---------------- launch ----------------------------------------------------
extern "C" void kernel_launch(void* const* d_in, const int* in_sizes, int n_in,
                              void* d_out, int out_size) {
    const float* x   = (const float*)d_in[0];
    const int*   src = (const int*)  d_in[1];
    const int*   dst = (const int*)  d_in[2];
    const float* Ws  = (const float*)d_in[3];
    const float* As  = (const float*)d_in[4];
    float* out = (float*)d_out;

    int N = in_sizes[0] / IN_F;   // 50000
    int E = in_sizes[1];          // 1600000

    // CSR build (by src)
    void* cnt_ptr = nullptr;
    cudaGetSymbolAddress(&cnt_ptr, g_cnt);
    cudaMemsetAsync(cnt_ptr, 0, (size_t)MAXN * sizeof(int));
    k_hist<<<(E + 255) / 256, 256>>>(src, E);
    int B = (N + 1023) / 1024;
    k_scan1<<<B, 1024>>>(N);
    k_scan2<<<1, 1>>>(B);
    k_scan3<<<B, 1024>>>(N);
    k_scatter<<<(E + 255) / 256, 256>>>(src, dst, E);

    // fused: feature transform (fp16 t) + attention weights exp(logit)
    cudaFuncSetAttribute(k_gemm, cudaFuncAttributeMaxDynamicSharedMemorySize,
                         GEMM_SMEM);
    dim3 gg((N + 127) / 128, HO / 128);
    k_gemm<<<gg, 256, GEMM_SMEM>>>(x, Ws, As, N);

    // softmax-weighted aggregation + ELU (2 nodes per block)
    k_agg<<<(N + 1) / 2, 256>>>(out, N);
}

// round 12
// speedup vs baseline: 1.4692x; 1.4692x over previous
#include <cuda_runtime.h>
#include <cuda_fp16.h>
#include <math.h>
#include <stdint.h>

// Problem constants (fixed by the dataset)
#define HEADS   8
#define OUT_F   64
#define HO      512          // HEADS * OUT_F
#define IN_F    256
#define MAXN    50048        // padded node count (multiple of 128)
#define MAXE    1600000

// ---------------- scratch (static __device__ globals, no runtime alloc) -----
__device__ __align__(16) static __half g_th[(size_t)MAXN * HO]; // 51.2 MB fp16 t (gather)
__device__ __align__(16) static float  g_w[(size_t)MAXN * HEADS]; // exp(logit)
__device__ static int g_cnt[MAXN];
__device__ static int g_rowptr[MAXN + 1];
__device__ static int g_cur[MAXN];
__device__ static int g_col[MAXE];
__device__ static int g_part[128];

// ---------------- CSR build -------------------------------------------------
__global__ void k_zero(int n) {
    int i = blockIdx.x * blockDim.x + threadIdx.x;
    if (i < n) g_cnt[i] = 0;
}

__global__ void k_hist(const int* __restrict__ src, int E) {
    int i = blockIdx.x * blockDim.x + threadIdx.x;
    if (i < E) atomicAdd(&g_cnt[src[i]], 1);
}

__global__ void k_scan1(int N) {
    __shared__ int s[1024];
    int tid = threadIdx.x;
    int i = blockIdx.x * 1024 + tid;
    int v = (i < N) ? g_cnt[i] : 0;
    s[tid] = v;
    __syncthreads();
    #pragma unroll
    for (int off = 1; off < 1024; off <<= 1) {
        int add = (tid >= off) ? s[tid - off] : 0;
        __syncthreads();
        s[tid] += add;
        __syncthreads();
    }
    if (i < N) g_rowptr[i + 1] = s[tid];
    if (tid == 1023) g_part[blockIdx.x] = s[1023];
}

__global__ void k_scan2(int B) {
    int run = 0;
    for (int b = 0; b < B; ++b) { int t = g_part[b]; g_part[b] = run; run += t; }
}

__global__ void k_scan3(int N) {
    int i = blockIdx.x * 1024 + threadIdx.x;
    if (i < N) {
        int rp = g_rowptr[i + 1] + g_part[blockIdx.x];
        g_rowptr[i + 1] = rp;
        if (i + 1 < N) g_cur[i + 1] = rp;
    }
    if (i == 0) { g_rowptr[0] = 0; g_cur[0] = 0; }
}

__global__ void k_scatter(const int* __restrict__ src, const int* __restrict__ dst, int E) {
    int i = blockIdx.x * blockDim.x + threadIdx.x;
    if (i < E) {
        int p = atomicAdd(&g_cur[src[i]], 1);
        g_col[p] = dst[i];
    }
}

// ---------------- tf32 MMA GEMM (cp.async double-buffered) ------------------
// t = x (M x 256) · Ws^T (256 x 512). BM=BN=128, BK=32, 2-stage pipeline.
// smem row-major [row][k] with pad 36 (36 mod 32 = 4 => fragment loads map
// addr%32 == lane: conflict-free). Fragments converted to tf32 with round-to-
// nearest (cvt.rna) at register load (validated: restores unbiased rounding,
// rel_err 8.9e-4 -> 3.6e-4). Epilogue: fp16 t store + fused exp(logit).
#define SMPAD 36
#define ABUF  4608            // 128*36 floats per stage
#define GEMM_SMEM ((2*ABUF*2 + 128 + 256) * 4)   // 75264 B

__device__ __forceinline__ void cp16(void* smem_dst, const void* gsrc, int nbytes) {
    uint32_t s = (uint32_t)__cvta_generic_to_shared(smem_dst);
    asm volatile("cp.async.ca.shared.global [%0], [%1], 16, %2;\n"
                 :: "r"(s), "l"(gsrc), "r"(nbytes));
}

__device__ __forceinline__ uint32_t rna(float x) {
    uint32_t u;
    asm("cvt.rna.tf32.f32 %0, %1;" : "=r"(u) : "f"(x));
    return u;
}

__global__ __launch_bounds__(256) void k_gemm(const float* __restrict__ A,
                                              const float* __restrict__ B,
                                              const float* __restrict__ As_in,
                                              int M) {
    extern __shared__ float dyn[];
    float* pA      = dyn;                 // [2][128][SMPAD]
    float* pB      = dyn + 2 * ABUF;      // [2][128][SMPAD]
    float* s_ar    = dyn + 4 * ABUF;      // [128]
    float* s_logit = s_ar + 128;          // [128][2]

    int tid  = threadIdx.x;
    int lane = tid & 31;
    int warp = tid >> 5;
    int wm   = (warp & 1) * 64;
    int wn   = (warp >> 1) * 32;
    int m0   = blockIdx.x * 128;
    int n0   = blockIdx.y * 128;

    if (tid < 128) {
        int c = n0 + tid;
        s_ar[tid] = As_in[(c >> 6) * 128 + 64 + (c & 63)];
    }
    s_logit[tid] = 0.f;   // 256 floats total, 256 threads

    float acc[4][4][4];
    #pragma unroll
    for (int mi = 0; mi < 4; ++mi)
        #pragma unroll
        for (int ni = 0; ni < 4; ++ni)
            #pragma unroll
            for (int j = 0; j < 4; ++j) acc[mi][ni][j] = 0.f;

    // stage issue: 128 rows x 32 floats for A and B = 1024 16B chunks each
    #define ISSUE(k0, buf)                                                     \
        do {                                                                   \
            _Pragma("unroll")                                                  \
            for (int r = 0; r < 4; ++r) {                                      \
                int id  = r * 256 + tid;                                       \
                int row = id >> 3;                                             \
                int c4  = (id & 7) * 4;                                        \
                cp16(&pA[(buf) * ABUF + row * SMPAD + c4],                     \
                     &A[(size_t)(m0 + row) * IN_F + (k0) + c4],                \
                     (m0 + row < M) ? 16 : 0);                                 \
                cp16(&pB[(buf) * ABUF + row * SMPAD + c4],                     \
                     &B[(size_t)(n0 + row) * IN_F + (k0) + c4], 16);           \
            }                                                                  \
            asm volatile("cp.async.commit_group;\n");                          \
        } while (0)

    ISSUE(0, 0);

    int lr = lane >> 2;   // 0..7
    int lc = lane & 3;    // 0..3

    for (int k0i = 0; k0i < 8; ++k0i) {
        int cur = k0i & 1;
        if (k0i < 7) {
            ISSUE((k0i + 1) * 32, cur ^ 1);
            asm volatile("cp.async.wait_group 1;\n");
        } else {
            asm volatile("cp.async.wait_group 0;\n");
        }
        __syncthreads();

        const float* Ab = pA + cur * ABUF;
        const float* Bb = pB + cur * ABUF;
        #pragma unroll
        for (int kk = 0; kk < 32; kk += 8) {
            uint32_t afr[4][4];
            uint32_t bfr[4][2];
            #pragma unroll
            for (int mi = 0; mi < 4; ++mi) {
                int rb = wm + mi * 16;
                afr[mi][0] = rna(Ab[(rb + lr    ) * SMPAD + kk + lc    ]);
                afr[mi][1] = rna(Ab[(rb + lr + 8) * SMPAD + kk + lc    ]);
                afr[mi][2] = rna(Ab[(rb + lr    ) * SMPAD + kk + lc + 4]);
                afr[mi][3] = rna(Ab[(rb + lr + 8) * SMPAD + kk + lc + 4]);
            }
            #pragma unroll
            for (int ni = 0; ni < 4; ++ni) {
                int nb = wn + ni * 8;
                bfr[ni][0] = rna(Bb[(nb + lr) * SMPAD + kk + lc    ]);
                bfr[ni][1] = rna(Bb[(nb + lr) * SMPAD + kk + lc + 4]);
            }
            #pragma unroll
            for (int mi = 0; mi < 4; ++mi)
                #pragma unroll
                for (int ni = 0; ni < 4; ++ni) {
                    asm volatile(
                        "mma.sync.aligned.m16n8k8.row.col.f32.tf32.tf32.f32 "
                        "{%0,%1,%2,%3}, {%4,%5,%6,%7}, {%8,%9}, {%0,%1,%2,%3};\n"
                        : "+f"(acc[mi][ni][0]), "+f"(acc[mi][ni][1]),
                          "+f"(acc[mi][ni][2]), "+f"(acc[mi][ni][3])
                        : "r"(afr[mi][0]), "r"(afr[mi][1]),
                          "r"(afr[mi][2]), "r"(afr[mi][3]),
                          "r"(bfr[ni][0]), "r"(bfr[ni][1]));
                }
        }
        __syncthreads();
    }

    // epilogue: fp16 t store + block-local logit reduction
    int head_local = warp >> 2;   // warps 0-3 -> head 0 of block; 4-7 -> head 1
    #pragma unroll
    for (int mi = 0; mi < 4; ++mi) {
        int r0 = m0 + wm + mi * 16 + lr;
        int r1 = r0 + 8;
        float p0 = 0.f, p1 = 0.f;
        #pragma unroll
        for (int ni = 0; ni < 4; ++ni) {
            int cl = wn + ni * 8 + lc * 2;    // block-local col
            int c  = n0 + cl;
            p0 = fmaf(acc[mi][ni][0], s_ar[cl], fmaf(acc[mi][ni][1], s_ar[cl + 1], p0));
            p1 = fmaf(acc[mi][ni][2], s_ar[cl], fmaf(acc[mi][ni][3], s_ar[cl + 1], p1));
            if (r0 < M)
                *(__half2*)&g_th[(size_t)r0 * HO + c] =
                    __floats2half2_rn(acc[mi][ni][0], acc[mi][ni][1]);
            if (r1 < M)
                *(__half2*)&g_th[(size_t)r1 * HO + c] =
                    __floats2half2_rn(acc[mi][ni][2], acc[mi][ni][3]);
        }
        atomicAdd(&s_logit[(wm + mi * 16 + lr    ) * 2 + head_local], p0);
        atomicAdd(&s_logit[(wm + mi * 16 + lr + 8) * 2 + head_local], p1);
    }
    __syncthreads();

    if (tid < 128 && m0 + tid < M) {
        int hb = blockIdx.y * 2;
        g_w[(size_t)(m0 + tid) * HEADS + hb    ] = expf(s_logit[tid * 2 + 0]);
        g_w[(size_t)(m0 + tid) * HEADS + hb + 1] = expf(s_logit[tid * 2 + 1]);
    }
}

// ---------------- aggregation + ELU (fp16 gather, post-normalize) -----------
// One block (128 thr) per node — the empirically fastest structure (R8).
// Thread j owns out[n, 4j..4j+3]; head h = j/16. Column indices staged through
// shared memory with __syncthreads.
// h[n] = (sum_e w_d * t_d) / (sum_e w_d): softmax normalization at the end
// (Al and the max-shift cancel in the ratio).
__global__ __launch_bounds__(128) void k_agg(float* __restrict__ out) {
    __shared__ int s_col[128];

    int n   = blockIdx.x;
    int tid = threadIdx.x;
    int rs  = g_rowptr[n];
    int re  = g_rowptr[n + 1];
    int h   = tid >> 4;

    if (re == rs) {  // no outgoing edges: out = elu(0) = 0
        *(float4*)&out[(size_t)n * HO + tid * 4] = make_float4(0.f, 0.f, 0.f, 0.f);
        return;
    }

    float  ws  = 0.f;
    float4 acc = make_float4(0.f, 0.f, 0.f, 0.f);
    const uint2* th2 = (const uint2*)g_th;   // 8 bytes = 4 fp16 per thread

    for (int base = rs; base < re; base += 128) {
        int nload = min(128, re - base);
        __syncthreads();
        if (tid < nload) s_col[tid] = __ldg(&g_col[base + tid]);
        __syncthreads();
        #pragma unroll 4
        for (int e = 0; e < nload; ++e) {
            int d = s_col[e];
            float wv = __ldg(&g_w[(size_t)d * 8 + h]);
            ws += wv;
            uint2 v = th2[(size_t)d * 128 + tid];   // coalesced 1KB row gather
            float2 f0 = __half22float2(*(__half2*)&v.x);
            float2 f1 = __half22float2(*(__half2*)&v.y);
            acc.x = fmaf(wv, f0.x, acc.x);
            acc.y = fmaf(wv, f0.y, acc.y);
            acc.z = fmaf(wv, f1.x, acc.z);
            acc.w = fmaf(wv, f1.y, acc.w);
        }
    }

    float inv = 1.f / ws;
    acc.x *= inv; acc.y *= inv; acc.z *= inv; acc.w *= inv;

    float4 r;
    r.x = acc.x > 0.f ? acc.x : expm1f(acc.x);
    r.y = acc.y > 0.f ? acc.y : expm1f(acc.y);
    r.z = acc.z > 0.f ? acc.z : expm1f(acc.z);
    r.w = acc.w > 0.f ? acc.w : expm1f(acc.w);
    __stcs((float4*)&out[(size_t)n * HO + tid * 4], r);  // stream out, keep t in L2
}

// ---------------- launch ----------------------------------------------------
extern "C" void kernel_launch(void* const* d_in, const int* in_sizes, int n_in,
                              void* d_out, int out_size) {
    const float* x   = (const float*)d_in[0];
    const int*   src = (const int*)  d_in[1];
    const int*   dst = (const int*)  d_in[2];
    const float* Ws  = (const float*)d_in[3];
    const float* As  = (const float*)d_in[4];
    float* out = (float*)d_out;

    int N = in_sizes[0] / IN_F;   // 50000
    int E = in_sizes[1];          // 1600000

    // CSR build (by src)
    k_zero<<<(N + 255) / 256, 256>>>(N);
    k_hist<<<(E + 255) / 256, 256>>>(src, E);
    int B = (N + 1023) / 1024;
    k_scan1<<<B, 1024>>>(N);
    k_scan2<<<1, 1>>>(B);
    k_scan3<<<B, 1024>>>(N);
    k_scatter<<<(E + 255) / 256, 256>>>(src, dst, E);

    // fused: feature transform (fp16 t) + attention weights exp(logit)
    cudaFuncSetAttribute(k_gemm, cudaFuncAttributeMaxDynamicSharedMemorySize,
                         GEMM_SMEM);
    dim3 gg((N + 127) / 128, HO / 128);
    k_gemm<<<gg, 256, GEMM_SMEM>>>(x, Ws, As, N);

    // softmax-weighted aggregation + ELU (one node per block)
    k_agg<<<N, 128>>>(out);
}

// round 13
// speedup vs baseline: 1.4924x; 1.0158x over previous
#include <cuda_runtime.h>
#include <cuda_fp16.h>
#include <math.h>
#include <stdint.h>

// Problem constants (fixed by the dataset)
#define HEADS   8
#define OUT_F   64
#define HO      512          // HEADS * OUT_F
#define IN_F    256
#define MAXN    50048        // padded node count (multiple of 128)
#define MAXE    1600000

// ---------------- scratch (static __device__ globals, no runtime alloc) -----
__device__ __align__(16) static __half g_th[(size_t)MAXN * HO]; // 51.2 MB fp16 t (gather)
__device__ __align__(16) static float  g_w[(size_t)MAXN * HEADS]; // exp(logit)
__device__ static int g_cnt[MAXN];
__device__ static int g_rowptr[MAXN];     // segment start per node (arbitrary order)
__device__ static int g_cur[MAXN];
__device__ static int g_col[MAXE];
__device__ static int g_cursor;

// ---------------- CSR build -------------------------------------------------
__global__ void k_zero(int n) {
    int i = blockIdx.x * blockDim.x + threadIdx.x;
    if (i < n) g_cnt[i] = 0;
    if (i == 0) g_cursor = 0;
}

__global__ void k_hist(const int* __restrict__ src, int E) {
    int i = blockIdx.x * blockDim.x + threadIdx.x;
    if (i < E) atomicAdd(&g_cnt[src[i]], 1);
}

// Fused segment allocation: block-local scan + one atomicAdd per block for the
// base. Segments land in block-arrival order — k_agg only needs [start,
// start+cnt) contiguous per node, not global ordering. Replaces the 3-kernel
// ordered scan (scan1 / serial scan2 / scan3).
__global__ void k_alloc(int N) {
    __shared__ int s[1024];
    __shared__ int s_base;
    int tid = threadIdx.x;
    int i = blockIdx.x * 1024 + tid;
    int v = (i < N) ? g_cnt[i] : 0;
    s[tid] = v;
    __syncthreads();
    #pragma unroll
    for (int off = 1; off < 1024; off <<= 1) {
        int add = (tid >= off) ? s[tid - off] : 0;
        __syncthreads();
        s[tid] += add;
        __syncthreads();
    }
    if (tid == 1023) s_base = atomicAdd(&g_cursor, s[1023]);
    __syncthreads();
    if (i < N) {
        int p = s_base + s[tid] - v;   // exclusive prefix + block base
        g_rowptr[i] = p;
        g_cur[i]    = p;
    }
}

__global__ void k_scatter(const int* __restrict__ src, const int* __restrict__ dst, int E) {
    int i = blockIdx.x * blockDim.x + threadIdx.x;
    if (i < E) {
        int p = atomicAdd(&g_cur[src[i]], 1);
        g_col[p] = dst[i];
    }
}

// ---------------- tf32 MMA GEMM (cp.async double-buffered) ------------------
// t = x (M x 256) · Ws^T (256 x 512). BM=BN=128, BK=32, 2-stage pipeline.
// smem row-major [row][k] with pad 36 (36 mod 32 = 4 => fragment loads map
// addr%32 == lane: conflict-free). Fragments converted to tf32 with round-to-
// nearest (cvt.rna) at register load (validated: restores unbiased rounding,
// rel_err 8.9e-4 -> 3.6e-4). Epilogue: fp16 t store + fused exp(logit).
#define SMPAD 36
#define ABUF  4608            // 128*36 floats per stage
#define GEMM_SMEM ((2*ABUF*2 + 128 + 256) * 4)   // 75264 B

__device__ __forceinline__ void cp16(void* smem_dst, const void* gsrc, int nbytes) {
    uint32_t s = (uint32_t)__cvta_generic_to_shared(smem_dst);
    asm volatile("cp.async.ca.shared.global [%0], [%1], 16, %2;\n"
                 :: "r"(s), "l"(gsrc), "r"(nbytes));
}

__device__ __forceinline__ uint32_t rna(float x) {
    uint32_t u;
    asm("cvt.rna.tf32.f32 %0, %1;" : "=r"(u) : "f"(x));
    return u;
}

__global__ __launch_bounds__(256) void k_gemm(const float* __restrict__ A,
                                              const float* __restrict__ B,
                                              const float* __restrict__ As_in,
                                              int M) {
    extern __shared__ float dyn[];
    float* pA      = dyn;                 // [2][128][SMPAD]
    float* pB      = dyn + 2 * ABUF;      // [2][128][SMPAD]
    float* s_ar    = dyn + 4 * ABUF;      // [128]
    float* s_logit = s_ar + 128;          // [128][2]

    int tid  = threadIdx.x;
    int lane = tid & 31;
    int warp = tid >> 5;
    int wm   = (warp & 1) * 64;
    int wn   = (warp >> 1) * 32;
    int m0   = blockIdx.x * 128;
    int n0   = blockIdx.y * 128;

    if (tid < 128) {
        int c = n0 + tid;
        s_ar[tid] = As_in[(c >> 6) * 128 + 64 + (c & 63)];
    }
    s_logit[tid] = 0.f;   // 256 floats total, 256 threads

    float acc[4][4][4];
    #pragma unroll
    for (int mi = 0; mi < 4; ++mi)
        #pragma unroll
        for (int ni = 0; ni < 4; ++ni)
            #pragma unroll
            for (int j = 0; j < 4; ++j) acc[mi][ni][j] = 0.f;

    // stage issue: 128 rows x 32 floats for A and B = 1024 16B chunks each
    #define ISSUE(k0, buf)                                                     \
        do {                                                                   \
            _Pragma("unroll")                                                  \
            for (int r = 0; r < 4; ++r) {                                      \
                int id  = r * 256 + tid;                                       \
                int row = id >> 3;                                             \
                int c4  = (id & 7) * 4;                                        \
                cp16(&pA[(buf) * ABUF + row * SMPAD + c4],                     \
                     &A[(size_t)(m0 + row) * IN_F + (k0) + c4],                \
                     (m0 + row < M) ? 16 : 0);                                 \
                cp16(&pB[(buf) * ABUF + row * SMPAD + c4],                     \
                     &B[(size_t)(n0 + row) * IN_F + (k0) + c4], 16);           \
            }                                                                  \
            asm volatile("cp.async.commit_group;\n");                          \
        } while (0)

    ISSUE(0, 0);

    int lr = lane >> 2;   // 0..7
    int lc = lane & 3;    // 0..3

    for (int k0i = 0; k0i < 8; ++k0i) {
        int cur = k0i & 1;
        if (k0i < 7) {
            ISSUE((k0i + 1) * 32, cur ^ 1);
            asm volatile("cp.async.wait_group 1;\n");
        } else {
            asm volatile("cp.async.wait_group 0;\n");
        }
        __syncthreads();

        const float* Ab = pA + cur * ABUF;
        const float* Bb = pB + cur * ABUF;
        #pragma unroll
        for (int kk = 0; kk < 32; kk += 8) {
            uint32_t afr[4][4];
            uint32_t bfr[4][2];
            #pragma unroll
            for (int mi = 0; mi < 4; ++mi) {
                int rb = wm + mi * 16;
                afr[mi][0] = rna(Ab[(rb + lr    ) * SMPAD + kk + lc    ]);
                afr[mi][1] = rna(Ab[(rb + lr + 8) * SMPAD + kk + lc    ]);
                afr[mi][2] = rna(Ab[(rb + lr    ) * SMPAD + kk + lc + 4]);
                afr[mi][3] = rna(Ab[(rb + lr + 8) * SMPAD + kk + lc + 4]);
            }
            #pragma unroll
            for (int ni = 0; ni < 4; ++ni) {
                int nb = wn + ni * 8;
                bfr[ni][0] = rna(Bb[(nb + lr) * SMPAD + kk + lc    ]);
                bfr[ni][1] = rna(Bb[(nb + lr) * SMPAD + kk + lc + 4]);
            }
            #pragma unroll
            for (int mi = 0; mi < 4; ++mi)
                #pragma unroll
                for (int ni = 0; ni < 4; ++ni) {
                    asm volatile(
                        "mma.sync.aligned.m16n8k8.row.col.f32.tf32.tf32.f32 "
                        "{%0,%1,%2,%3}, {%4,%5,%6,%7}, {%8,%9}, {%0,%1,%2,%3};\n"
                        : "+f"(acc[mi][ni][0]), "+f"(acc[mi][ni][1]),
                          "+f"(acc[mi][ni][2]), "+f"(acc[mi][ni][3])
                        : "r"(afr[mi][0]), "r"(afr[mi][1]),
                          "r"(afr[mi][2]), "r"(afr[mi][3]),
                          "r"(bfr[ni][0]), "r"(bfr[ni][1]));
                }
        }
        __syncthreads();
    }

    // epilogue: fp16 t store + block-local logit reduction
    int head_local = warp >> 2;   // warps 0-3 -> head 0 of block; 4-7 -> head 1
    #pragma unroll
    for (int mi = 0; mi < 4; ++mi) {
        int r0 = m0 + wm + mi * 16 + lr;
        int r1 = r0 + 8;
        float p0 = 0.f, p1 = 0.f;
        #pragma unroll
        for (int ni = 0; ni < 4; ++ni) {
            int cl = wn + ni * 8 + lc * 2;    // block-local col
            int c  = n0 + cl;
            p0 = fmaf(acc[mi][ni][0], s_ar[cl], fmaf(acc[mi][ni][1], s_ar[cl + 1], p0));
            p1 = fmaf(acc[mi][ni][2], s_ar[cl], fmaf(acc[mi][ni][3], s_ar[cl + 1], p1));
            if (r0 < M)
                *(__half2*)&g_th[(size_t)r0 * HO + c] =
                    __floats2half2_rn(acc[mi][ni][0], acc[mi][ni][1]);
            if (r1 < M)
                *(__half2*)&g_th[(size_t)r1 * HO + c] =
                    __floats2half2_rn(acc[mi][ni][2], acc[mi][ni][3]);
        }
        atomicAdd(&s_logit[(wm + mi * 16 + lr    ) * 2 + head_local], p0);
        atomicAdd(&s_logit[(wm + mi * 16 + lr + 8) * 2 + head_local], p1);
    }
    __syncthreads();

    if (tid < 128 && m0 + tid < M) {
        int hb = blockIdx.y * 2;
        g_w[(size_t)(m0 + tid) * HEADS + hb    ] = expf(s_logit[tid * 2 + 0]);
        g_w[(size_t)(m0 + tid) * HEADS + hb + 1] = expf(s_logit[tid * 2 + 1]);
    }
}

// ---------------- aggregation + ELU (fp16 gather, post-normalize) -----------
// One block (128 thr) per node — the empirically fastest structure (R8).
// Thread j owns out[n, 4j..4j+3]; head h = j/16. Column indices staged through
// shared memory with __syncthreads. Segment = [rowptr[n], rowptr[n]+cnt[n]).
// h[n] = (sum_e w_d * t_d) / (sum_e w_d): softmax normalization at the end
// (Al and the max-shift cancel in the ratio).
__global__ __launch_bounds__(128) void k_agg(float* __restrict__ out) {
    __shared__ int s_col[128];

    int n   = blockIdx.x;
    int tid = threadIdx.x;
    int rs  = g_rowptr[n];
    int re  = rs + g_cnt[n];
    int h   = tid >> 4;

    if (re == rs) {  // no outgoing edges: out = elu(0) = 0
        *(float4*)&out[(size_t)n * HO + tid * 4] = make_float4(0.f, 0.f, 0.f, 0.f);
        return;
    }

    float  ws  = 0.f;
    float4 acc = make_float4(0.f, 0.f, 0.f, 0.f);
    const uint2* th2 = (const uint2*)g_th;   // 8 bytes = 4 fp16 per thread

    for (int base = rs; base < re; base += 128) {
        int nload = min(128, re - base);
        __syncthreads();
        if (tid < nload) s_col[tid] = __ldg(&g_col[base + tid]);
        __syncthreads();
        #pragma unroll 4
        for (int e = 0; e < nload; ++e) {
            int d = s_col[e];
            float wv = __ldg(&g_w[(size_t)d * 8 + h]);
            ws += wv;
            uint2 v = th2[(size_t)d * 128 + tid];   // coalesced 1KB row gather
            float2 f0 = __half22float2(*(__half2*)&v.x);
            float2 f1 = __half22float2(*(__half2*)&v.y);
            acc.x = fmaf(wv, f0.x, acc.x);
            acc.y = fmaf(wv, f0.y, acc.y);
            acc.z = fmaf(wv, f1.x, acc.z);
            acc.w = fmaf(wv, f1.y, acc.w);
        }
    }

    float inv = 1.f / ws;
    acc.x *= inv; acc.y *= inv; acc.z *= inv; acc.w *= inv;

    float4 r;
    r.x = acc.x > 0.f ? acc.x : expm1f(acc.x);
    r.y = acc.y > 0.f ? acc.y : expm1f(acc.y);
    r.z = acc.z > 0.f ? acc.z : expm1f(acc.z);
    r.w = acc.w > 0.f ? acc.w : expm1f(acc.w);
    __stcs((float4*)&out[(size_t)n * HO + tid * 4], r);  // stream out, keep t in L2
}

// ---------------- launch ----------------------------------------------------
extern "C" void kernel_launch(void* const* d_in, const int* in_sizes, int n_in,
                              void* d_out, int out_size) {
    const float* x   = (const float*)d_in[0];
    const int*   src = (const int*)  d_in[1];
    const int*   dst = (const int*)  d_in[2];
    const float* Ws  = (const float*)d_in[3];
    const float* As  = (const float*)d_in[4];
    float* out = (float*)d_out;

    int N = in_sizes[0] / IN_F;   // 50000
    int E = in_sizes[1];          // 1600000

    // CSR build (by src): zero -> hist -> fused alloc -> scatter
    k_zero<<<(N + 255) / 256, 256>>>(N);
    k_hist<<<(E + 255) / 256, 256>>>(src, E);
    k_alloc<<<(N + 1023) / 1024, 1024>>>(N);
    k_scatter<<<(E + 255) / 256, 256>>>(src, dst, E);

    // fused: feature transform (fp16 t) + attention weights exp(logit)
    cudaFuncSetAttribute(k_gemm, cudaFuncAttributeMaxDynamicSharedMemorySize,
                         GEMM_SMEM);
    dim3 gg((N + 127) / 128, HO / 128);
    k_gemm<<<gg, 256, GEMM_SMEM>>>(x, Ws, As, N);

    // softmax-weighted aggregation + ELU (one node per block)
    k_agg<<<N, 128>>>(out);
}